// round 9
// baseline (speedup 1.0000x reference)
#include <cuda_runtime.h>
#include <cstdint>

#define NEG   (-1e30f)
#define LOG2E (1.4426950408889634f)
#define LN2   (0.6931471805599453f)

// Fixed problem shape (B=32, T=1024, V=1000, L=128); scratch sized to max.
#define MAXB 32
#define MAXT 1024
#define MAXL 128
#define ESTR 132     // padded emission row stride (floats): 129 used
#define RING 32
#define RMASK 31

// Static scratch (no allocation allowed anywhere).
__device__ float g_emit[(size_t)MAXB * MAXT * ESTR];
__device__ float g_res[MAXB];

__device__ __forceinline__ float lse3_2(float a, float b, float c) {
    // logsumexp in log2 domain: m + log2(2^(a-m)+2^(b-m)+2^(c-m))
    float m = fmaxf(a, fmaxf(b, c));
    float s = exp2f(a - m) + exp2f(b - m) + exp2f(c - m);
    return m + __log2f(s);
}

// ---------------------------------------------------------------------------
// Kernel A: one WARP per (b,t) row. Single pass over V=1000 in registers,
// warp-shuffle reductions only. Emits log2-domain log-softmax for the 129
// needed tokens (blank + L labels) into g_emit.
// ---------------------------------------------------------------------------
__global__ void __launch_bounds__(128) lse_gather_kernel(
    const float* __restrict__ pred,
    const int*   __restrict__ target,
    int T, int V, int L, int nrows)
{
    const int warp = blockIdx.x * (blockDim.x >> 5) + (threadIdx.x >> 5);
    if (warp >= nrows) return;
    const int lane = threadIdx.x & 31;
    const int b = warp / T;

    const float* __restrict__ row = pred + (size_t)warp * V;
    const float4* __restrict__ row4 = (const float4*)row;
    const int nvec = V >> 2;     // 250

    float4 v[8];
    #pragma unroll
    for (int i = 0; i < 8; ++i) {
        const int idx = lane + (i << 5);
        v[i] = (idx < nvec) ? row4[idx] : make_float4(NEG, NEG, NEG, NEG);
    }

    float m = NEG;
    #pragma unroll
    for (int i = 0; i < 8; ++i)
        m = fmaxf(m, fmaxf(fmaxf(v[i].x, v[i].y), fmaxf(v[i].z, v[i].w)));
    #pragma unroll
    for (int o = 16; o > 0; o >>= 1) m = fmaxf(m, __shfl_xor_sync(0xffffffffu, m, o));

    const float m2 = m * LOG2E;
    float sum = 0.f;
    #pragma unroll
    for (int i = 0; i < 8; ++i) {
        sum += exp2f(fmaf(v[i].x, LOG2E, -m2)) + exp2f(fmaf(v[i].y, LOG2E, -m2))
             + exp2f(fmaf(v[i].z, LOG2E, -m2)) + exp2f(fmaf(v[i].w, LOG2E, -m2));
    }
    #pragma unroll
    for (int o = 16; o > 0; o >>= 1) sum += __shfl_xor_sync(0xffffffffu, sum, o);

    const float lse2 = m2 + __log2f(sum);   // log2(sum_v exp(x_v))

    float* __restrict__ erow = g_emit + (size_t)warp * ESTR;
    const int* __restrict__ tgt = target + (size_t)b * L;
    for (int j = lane; j <= L; j += 32) {
        const int tok = (j == 0) ? 0 : tgt[j - 1];
        erow[j] = fmaf(row[tok], LOG2E, -lse2);
    }
}

// ---------------------------------------------------------------------------
// Kernel B: W-CTC forward DP as a SYSTOLIC WARP PIPELINE. One block per batch,
// one thread per state (288 thr, 9 warps), alpha in registers, intra-warp
// neighbors via shfl_up. CTC deps point only downward, so warps run
// time-skewed with NO block barriers in the main loop: each warp publishes its
// top-2 alphas per step as (tag||value) 64-bit volatile shared words into a
// 32-deep ring; the next warp's lanes 0-1 spin-consume them. Backpressure via
// per-warp progress counters (checked every 8 steps). Emissions prefetched
// per-lane through a depth-4 register queue. endstar accumulated in-register
// by the warp owning states ll/lb.
// ---------------------------------------------------------------------------
__global__ void __launch_bounds__(288) wctc_dp_kernel(
    const int* __restrict__ target,
    const int* __restrict__ tlen,
    int T, int L)
{
    const int b    = blockIdx.x;
    const int tid  = threadIdx.x;
    const int lane = tid & 31;
    const int w    = tid >> 5;            // 9 warps

    __shared__ unsigned long long bnd[8][RING][2];  // producer warps 0..7
    __shared__ int prog[9];
    __shared__ int tg[MAXL];

    for (int k = tid; k < L; k += 288) tg[k] = target[(size_t)b * L + k];
    for (int k = tid; k < 8 * RING * 2; k += 288)
        ((unsigned long long*)bnd)[k] = ~0ull;      // poison tags
    if (tid < 9) prog[tid] = 0;
    __syncthreads();                                // one-time init barrier

    const int  tl     = tlen[b];
    const int  s      = tid;
    const bool active = (s < 2 * L + 2);            // 258 states
    const bool odd    = (s & 1) != 0;
    const bool valid  = (s <= 2 * tl + 1);
    bool skipOK = false;
    if (active && !odd && s >= 2)
        skipOK = (s == 2) || (tg[(s >> 1) - 1] != tg[(s >> 1) - 2]);

    const int  j     = (active && !odd) ? (s >> 1) : 0;  // emission column
    const float* __restrict__ erow = g_emit + (size_t)b * T * ESTR;
    const float* __restrict__ ep   = erow + j;

    const int  ll = 2 * tl;
    const int  wOwn = ll >> 5, lOwn = ll & 31;
    const bool ownerWarp = (w == wOwn);

    // ---- t = 0 init (alpha in register) ----
    float alpha;
    if (s == 0)      alpha = 0.f;
    else if (s == 1) alpha = erow[0];
    else if (s == 2) alpha = erow[1];
    else             alpha = NEG;
    if (!valid)      alpha = NEG;
    float es = NEG;

    // publish t=0 boundary; accumulate endstar for t=0
    if (w < 8 && lane >= 30)
        *(volatile unsigned long long*)&bnd[w][0][lane - 30] =
            __float_as_uint(alpha);                  // tag 0 in high bits
    if (ownerWarp) {
        float aLb = __shfl_down_sync(0xffffffffu, alpha, 1);
        if (lane == lOwn) es = lse3_2(es, alpha, aLb);
    }

#define EV(x) (ep[(size_t)((x) < T - 1 ? (x) : (T - 1)) * ESTR])

#define STEP(tt, ee) do {                                                     \
    if ((((tt) & 7) == 1) && w < 8 && lane == 0) {                            \
        while (*(volatile int*)&prog[w + 1] < (tt) - 24) { }                  \
    }                                                                         \
    float b30 = NEG, b31 = NEG;                                               \
    if (w > 0 && lane < 2) {                                                  \
        const int slot = ((tt) - 1) & RMASK;                                  \
        volatile unsigned long long* p0 = (volatile unsigned long long*)&bnd[w - 1][slot][0]; \
        volatile unsigned long long* p1 = (volatile unsigned long long*)&bnd[w - 1][slot][1]; \
        const unsigned tagw = (unsigned)((tt) - 1);                           \
        unsigned long long v0, v1;                                            \
        do { v0 = *p0; v1 = *p1;                                              \
        } while ((unsigned)(v0 >> 32) != tagw || (unsigned)(v1 >> 32) != tagw); \
        b30 = __uint_as_float((unsigned)v0);                                  \
        b31 = __uint_as_float((unsigned)v1);                                  \
    }                                                                         \
    float nb1 = __shfl_up_sync(0xffffffffu, alpha, 1);                        \
    float nb2 = __shfl_up_sync(0xffffffffu, alpha, 2);                        \
    if (w > 0) {                                                              \
        if (lane == 0) { nb1 = b31; nb2 = b30; }                              \
        else if (lane == 1) { nb2 = b31; }                                    \
    } else {                                                                  \
        if (lane == 1) nb2 = NEG;                                             \
    }                                                                         \
    const float p2v = skipOK ? nb2 : NEG;                                     \
    float na = (ee) + lse3_2(alpha, nb1, p2v);                                \
    if (s == 0) na = 0.f;                                                     \
    if (!valid) na = NEG;                                                     \
    alpha = na;                                                               \
    if (w < 8 && lane >= 30)                                                  \
        *(volatile unsigned long long*)&bnd[w][(tt) & RMASK][lane - 30] =     \
            ((unsigned long long)(unsigned)(tt) << 32) | __float_as_uint(alpha); \
    if (ownerWarp) {                                                          \
        float aLb = __shfl_down_sync(0xffffffffu, alpha, 1);                  \
        if (lane == lOwn) es = lse3_2(es, alpha, aLb);                        \
    }                                                                         \
    if (lane == 0) *(volatile int*)&prog[w] = (tt);                           \
} while (0)

    // Emission register queue, depth 4
    float eq0 = EV(1), eq1 = EV(2), eq2 = EV(3), eq3 = EV(4);

    int t = 1;
    for (; t + 3 <= T - 1; t += 4) {
        STEP(t,     eq0); eq0 = EV(t + 4);
        STEP(t + 1, eq1); eq1 = EV(t + 5);
        STEP(t + 2, eq2); eq2 = EV(t + 6);
        STEP(t + 3, eq3); eq3 = EV(t + 7);
    }
    for (; t <= T - 1; ++t) { float e1 = EV(t); STEP(t, e1); }

#undef STEP
#undef EV

    if (ownerWarp && lane == lOwn)
        g_res[b] = (-es * LN2) / (float)tl;          // nll / target_length
}

// ---------------------------------------------------------------------------
// Kernel C: mean over batch -> scalar output.
// ---------------------------------------------------------------------------
__global__ void __launch_bounds__(32) finalize_kernel(float* __restrict__ out, int B)
{
    float v = 0.f;
    for (int i = threadIdx.x; i < B; i += 32) v += g_res[i];
    #pragma unroll
    for (int o = 16; o > 0; o >>= 1) v += __shfl_xor_sync(0xffffffffu, v, o);
    if (threadIdx.x == 0) out[0] = v / (float)B;
}

extern "C" void kernel_launch(void* const* d_in, const int* in_sizes, int n_in,
                              void* d_out, int out_size)
{
    const float* pred   = (const float*)d_in[0];   // (B,T,V) fp32
    const int*   target = (const int*)d_in[1];     // (B,L)  int32
    const int*   tlen   = (const int*)d_in[2];     // (B,)   int32

    const int B = in_sizes[2];
    const int L = in_sizes[1] / B;
    const int V = 1000;
    const int T = in_sizes[0] / (B * V);
    const int nrows = B * T;

    lse_gather_kernel<<<(nrows + 3) / 4, 128>>>(pred, target, T, V, L, nrows);
    wctc_dp_kernel<<<B, 288>>>(target, tlen, T, L);
    finalize_kernel<<<1, 32>>>((float*)d_out, B);
}

// round 10
// speedup vs baseline: 4.8382x; 4.8382x over previous
#include <cuda_runtime.h>
#include <cstdint>

#define NEG   (-1e30f)
#define LOG2E (1.4426950408889634f)
#define LN2   (0.6931471805599453f)
#define FULLMASK 0xffffffffu

// Fixed problem shape (B=32, T=1024, V=1000, L=128); scratch sized to max.
#define MAXB 32
#define MAXT 1024
#define MAXL 128
#define ESTR 132     // padded emission row stride (floats): 129 used
#define CH   8       // timesteps staged per SMEM chunk
#define CHF  (CH * ESTR)        // floats per chunk (1056)
#define CHV  (CHF / 4)          // float4 per chunk (264)

// Static scratch (no allocation allowed anywhere).
__device__ float g_emit[(size_t)MAXB * MAXT * ESTR];
__device__ float g_res[MAXB];

__device__ __forceinline__ float ex2a(float x) {
    float r; asm("ex2.approx.ftz.f32 %0, %1;" : "=f"(r) : "f"(x)); return r;
}
__device__ __forceinline__ float lg2a(float x) {
    float r; asm("lg2.approx.ftz.f32 %0, %1;" : "=f"(r) : "f"(x)); return r;
}
__device__ __forceinline__ float lse3_2(float a, float b, float c) {
    // logsumexp in log2 domain: m + log2(2^(a-m)+2^(b-m)+2^(c-m))
    float m = fmaxf(a, fmaxf(b, c));
    float s = ex2a(a - m) + ex2a(b - m) + ex2a(c - m);
    return m + lg2a(s);
}

// ---------------------------------------------------------------------------
// Kernel A: one WARP per (b,t) row. Single pass over V=1000 in registers,
// warp-shuffle reductions only. Emits log2-domain log-softmax for the 129
// needed tokens (blank + L labels) into g_emit.
// ---------------------------------------------------------------------------
__global__ void __launch_bounds__(128) lse_gather_kernel(
    const float* __restrict__ pred,
    const int*   __restrict__ target,
    int T, int V, int L, int nrows)
{
    const int warp = blockIdx.x * (blockDim.x >> 5) + (threadIdx.x >> 5);
    if (warp >= nrows) return;
    const int lane = threadIdx.x & 31;
    const int b = warp / T;

    const float* __restrict__ row = pred + (size_t)warp * V;
    const float4* __restrict__ row4 = (const float4*)row;
    const int nvec = V >> 2;     // 250

    float4 v[8];
    #pragma unroll
    for (int i = 0; i < 8; ++i) {
        const int idx = lane + (i << 5);
        v[i] = (idx < nvec) ? row4[idx] : make_float4(NEG, NEG, NEG, NEG);
    }

    float m = NEG;
    #pragma unroll
    for (int i = 0; i < 8; ++i)
        m = fmaxf(m, fmaxf(fmaxf(v[i].x, v[i].y), fmaxf(v[i].z, v[i].w)));
    #pragma unroll
    for (int o = 16; o > 0; o >>= 1) m = fmaxf(m, __shfl_xor_sync(FULLMASK, m, o));

    const float m2 = m * LOG2E;
    float sum = 0.f;
    #pragma unroll
    for (int i = 0; i < 8; ++i) {
        sum += ex2a(fmaf(v[i].x, LOG2E, -m2)) + ex2a(fmaf(v[i].y, LOG2E, -m2))
             + ex2a(fmaf(v[i].z, LOG2E, -m2)) + ex2a(fmaf(v[i].w, LOG2E, -m2));
    }
    #pragma unroll
    for (int o = 16; o > 0; o >>= 1) sum += __shfl_xor_sync(FULLMASK, sum, o);

    const float lse2 = m2 + lg2a(sum);   // log2(sum_v exp(x_v))

    float* __restrict__ erow = g_emit + (size_t)warp * ESTR;
    const int* __restrict__ tgt = target + (size_t)b * L;
    for (int j = lane; j <= L; j += 32) {
        const int tok = (j == 0) ? 0 : tgt[j - 1];
        erow[j] = fmaf(row[tok], LOG2E, -lse2);
    }
}

// ---------------------------------------------------------------------------
// Kernel B: W-CTC forward DP, one block per batch, one thread per state
// (288 thr). TWO timesteps per barrier (trapezoid): level t read from shared
// (as R6), level t+1 built in registers via shfl_up with a 2-wide halo
// redundantly computed by lanes 0-1 of each warp. Emissions staged through a
// double-buffered SMEM chunk of 8 timesteps. endstar handled by an idle tail
// thread that self-computes the intermediate level's ll/lb states.
// ---------------------------------------------------------------------------
#define HELPER_TID 264

__global__ void __launch_bounds__(288) wctc_dp_kernel(
    const int* __restrict__ target,
    const int* __restrict__ tlen,
    int T, int L)
{
    const int b    = blockIdx.x;
    const int tid  = threadIdx.x;
    const int lane = tid & 31;
    const int w    = tid >> 5;

    __shared__ float buf[2][2 * MAXL + 4];   // alpha; idx s+2, [0..1]=NEG sentinel
    __shared__ float e_sh[2][CHF];           // staged emission chunks
    __shared__ int   tg[MAXL];

    for (int k = tid; k < L; k += 288) tg[k] = target[(size_t)b * L + k];
    if (tid < 2) { buf[0][tid] = NEG; buf[1][tid] = NEG; }
    __syncthreads();

    const int  tl     = tlen[b];
    const int  s      = tid;
    const bool active = (s < 2 * L + 2);             // 258 states
    const bool odd    = (s & 1) != 0;
    const bool valid  = (s <= 2 * tl + 1);
    bool skipOK = false;
    if (active && !odd && s >= 2)
        skipOK = (s == 2) || (tg[(s >> 1) - 1] != tg[(s >> 1) - 2]);
    const int j = (active && !odd) ? (s >> 1) : 0;   // emission column

    // Halo (level t+1 values for states base-2, base-1) computed by lanes 0,1
    const int  base    = w << 5;
    const bool haloAct = (w > 0) && (lane < 2);
    int  sh = 0, jh = 0; bool hValid = false, hSkip = false;
    if (haloAct) {
        sh = base - 2 + lane;                        // lane0: even label, lane1: odd blank
        jh = (lane == 0) ? (sh >> 1) : 0;
        hValid = (sh <= 2 * tl + 1);
        if (lane == 0) hSkip = (tg[(sh >> 1) - 1] != tg[(sh >> 1) - 2]);
    }

    const bool isHelper = (tid == HELPER_TID);
    const int  ll = 2 * tl, lb = ll + 1, jLL = tl;
    const bool skipLL = (tg[tl - 1] != tg[tl - 2]);

    const float*  __restrict__ erow  = g_emit + (size_t)b * T * ESTR;
    const float4* __restrict__ erow4 = (const float4*)erow;

    // ---- t = 0 init into buf[0] ----
    if (active) {
        float a0 = NEG;
        if (s == 0)      a0 = 0.f;
        else if (s == 1) a0 = erow[0];
        else if (s == 2) a0 = erow[1];
        if (!valid)      a0 = NEG;
        buf[0][s + 2] = a0;
    }
    float es = NEG;                                  // endstar acc (helper only)

    // Preload chunk 0
    float4 ld = make_float4(0.f, 0.f, 0.f, 0.f);
    if (tid < CHV) ld = erow4[tid];

    int cur = 0;

#define SSTEP(E1) do {                                                        \
    float* C  = buf[cur]; float* Nx = buf[cur ^ 1];                           \
    if (active) {                                                             \
        float p2 = skipOK ? C[s] : NEG;                                       \
        float a1 = (E1)[j] + lse3_2(C[s + 2], C[s + 1], p2);                  \
        if (s == 0) a1 = 0.f;                                                 \
        if (!valid) a1 = NEG;                                                 \
        Nx[s + 2] = a1;                                                       \
    }                                                                         \
    if (isHelper) es = lse3_2(es, C[ll + 2], C[lb + 2]);                      \
    __syncthreads(); cur ^= 1;                                                \
} while (0)

#define PAIR(E1, E2) do {                                                     \
    float* C  = buf[cur]; float* Nx = buf[cur ^ 1];                           \
    float a1 = NEG, h = NEG;                                                  \
    if (active) {                                                             \
        float p2 = skipOK ? C[s] : NEG;                                       \
        a1 = (E1)[j] + lse3_2(C[s + 2], C[s + 1], p2);                        \
        if (s == 0) a1 = 0.f;                                                 \
        if (!valid) a1 = NEG;                                                 \
    }                                                                         \
    if (haloAct) {                                                            \
        float hp2 = hSkip ? C[sh] : NEG;                                      \
        h = (E1)[jh] + lse3_2(C[sh + 2], C[sh + 1], hp2);                     \
        if (!hValid) h = NEG;                                                 \
    }                                                                         \
    float nb1 = __shfl_up_sync(FULLMASK, a1, 1);                              \
    float nb2 = __shfl_up_sync(FULLMASK, a1, 2);                              \
    float hB  = __shfl_sync(FULLMASK, h, 1);                                  \
    if (lane == 0)      { nb1 = hB; nb2 = h; }                                \
    else if (lane == 1) { nb2 = hB; }                                         \
    if (active) {                                                             \
        float p2 = skipOK ? nb2 : NEG;                                        \
        float a2 = (E2)[j] + lse3_2(a1, nb1, p2);                             \
        if (s == 0) a2 = 0.f;                                                 \
        if (!valid) a2 = NEG;                                                 \
        Nx[s + 2] = a2;                                                       \
    }                                                                         \
    if (isHelper) {                                                           \
        float cll = C[ll + 2], clb = C[lb + 2];                               \
        float c1  = C[ll + 1], c0  = C[ll];                                   \
        es = lse3_2(es, cll, clb);                                            \
        float a1ll = (E1)[jLL] + lse3_2(cll, c1, skipLL ? c0 : NEG);          \
        float a1lb = (E1)[0]   + lse3_2(clb, cll, NEG);                       \
        es = lse3_2(es, a1ll, a1lb);                                          \
    }                                                                         \
    __syncthreads(); cur ^= 1;                                                \
} while (0)

    const int nchunks = T / CH;          // 128

    // ---- chunk 0 (t=0 already done; single step t=1, then pairs) ----
    {
        if (tid < CHV) ((float4*)e_sh[0])[tid] = ld;
        if (tid < CHV) ld = erow4[(size_t)CHV + tid];
        __syncthreads();
        const float* E = e_sh[0];
        SSTEP(E + 1 * ESTR);
        PAIR(E + 2 * ESTR, E + 3 * ESTR);
        PAIR(E + 4 * ESTR, E + 5 * ESTR);
        PAIR(E + 6 * ESTR, E + 7 * ESTR);
    }

    // ---- chunks 1..nchunks-1 ----
    for (int c = 1; c < nchunks; ++c) {
        const int pb = c & 1;
        if (tid < CHV) ((float4*)e_sh[pb])[tid] = ld;
        if (c + 1 < nchunks && tid < CHV)
            ld = erow4[(size_t)(c + 1) * CHV + tid];
        __syncthreads();
        const float* E = e_sh[pb];
        PAIR(E + 0 * ESTR, E + 1 * ESTR);
        PAIR(E + 2 * ESTR, E + 3 * ESTR);
        PAIR(E + 4 * ESTR, E + 5 * ESTR);
        PAIR(E + 6 * ESTR, E + 7 * ESTR);
    }

#undef SSTEP
#undef PAIR

    if (isHelper) {
        float* C = buf[cur];
        const float tot2 = lse3_2(C[ll + 2], C[lb + 2], es);  // log2 total
        g_res[b] = (-tot2 * LN2) / (float)tl;                 // nll / target_length
    }
}

// ---------------------------------------------------------------------------
// Kernel C: mean over batch -> scalar output.
// ---------------------------------------------------------------------------
__global__ void __launch_bounds__(32) finalize_kernel(float* __restrict__ out, int B)
{
    float v = 0.f;
    for (int i = threadIdx.x; i < B; i += 32) v += g_res[i];
    #pragma unroll
    for (int o = 16; o > 0; o >>= 1) v += __shfl_xor_sync(FULLMASK, v, o);
    if (threadIdx.x == 0) out[0] = v / (float)B;
}

extern "C" void kernel_launch(void* const* d_in, const int* in_sizes, int n_in,
                              void* d_out, int out_size)
{
    const float* pred   = (const float*)d_in[0];   // (B,T,V) fp32
    const int*   target = (const int*)d_in[1];     // (B,L)  int32
    const int*   tlen   = (const int*)d_in[2];     // (B,)   int32

    const int B = in_sizes[2];
    const int L = in_sizes[1] / B;
    const int V = 1000;
    const int T = in_sizes[0] / (B * V);
    const int nrows = B * T;

    lse_gather_kernel<<<(nrows + 3) / 4, 128>>>(pred, target, T, V, L, nrows);
    wctc_dp_kernel<<<B, 288>>>(target, tlen, T, L);
    finalize_kernel<<<1, 32>>>((float*)d_out, B);
}